// round 13
// baseline (speedup 1.0000x reference)
#include <cuda_runtime.h>
#include <cuda_fp16.h>
#include <math.h>
#include <cstdint>

#define BATCH  4
#define SEQ    1024
#define DMODEL 1024
#define NH     16
#define DK     64
#define LOG2E  1.4426950408889634f

// ---------------- scratch (device globals: allocation-free) ----------------
__device__ __half g_xh[BATCH * SEQ * DMODEL];
__device__ __half g_WTh[4 * 1024 * 1024];     // W^T per matrix: [n][k] fp16
__device__ __half g_Qh[BATCH * NH * SEQ * DK];
__device__ __half g_Kh[BATCH * NH * SEQ * DK];
__device__ __half g_Vh[BATCH * NH * SEQ * DK];
__device__ __half g_ctxh[BATCH * SEQ * DMODEL];
__device__ __half g_biash[(size_t)BATCH * NH * SEQ * SEQ];  // bias*log2e, mask folded

// ---------------- helpers ----------------
__device__ __forceinline__ void mma_f16(float c[4], const uint32_t a[4], const uint32_t b[2]) {
    asm volatile("mma.sync.aligned.m16n8k16.row.col.f32.f16.f16.f32 "
                 "{%0,%1,%2,%3}, {%4,%5,%6,%7}, {%8,%9}, {%0,%1,%2,%3};"
                 : "+f"(c[0]), "+f"(c[1]), "+f"(c[2]), "+f"(c[3])
                 : "r"(a[0]), "r"(a[1]), "r"(a[2]), "r"(a[3]), "r"(b[0]), "r"(b[1]));
}
// fp16-C accumulator variant: C/D are 2 half2 regs (row r, row r+8)
__device__ __forceinline__ void mma_f16c(uint32_t c[2], const uint32_t a[4], const uint32_t b[2]) {
    asm volatile("mma.sync.aligned.m16n8k16.row.col.f16.f16.f16.f16 "
                 "{%0,%1}, {%2,%3,%4,%5}, {%6,%7}, {%0,%1};"
                 : "+r"(c[0]), "+r"(c[1])
                 : "r"(a[0]), "r"(a[1]), "r"(a[2]), "r"(a[3]), "r"(b[0]), "r"(b[1]));
}
__device__ __forceinline__ uint32_t smem_u32(const void* p) {
    uint32_t a;
    asm("{ .reg .u64 t; cvta.to.shared.u64 t, %1; cvt.u32.u64 %0, t; }" : "=r"(a) : "l"(p));
    return a;
}
__device__ __forceinline__ void cp_async16(uint32_t s, const void* g) {
    asm volatile("cp.async.cg.shared.global [%0], [%1], 16;" :: "r"(s), "l"(g) : "memory");
}
__device__ __forceinline__ void cp_commit() {
    asm volatile("cp.async.commit_group;" ::: "memory");
}
__device__ __forceinline__ void cp_wait0() {
    asm volatile("cp.async.wait_group 0;" ::: "memory");
}
__device__ __forceinline__ void cp_wait1() {
    asm volatile("cp.async.wait_group 1;" ::: "memory");
}
__device__ __forceinline__ void ldsm_x4(uint32_t& d0, uint32_t& d1, uint32_t& d2, uint32_t& d3,
                                        uint32_t addr) {
    asm volatile("ldmatrix.sync.aligned.m8n8.x4.shared.b16 {%0,%1,%2,%3}, [%4];"
                 : "=r"(d0), "=r"(d1), "=r"(d2), "=r"(d3) : "r"(addr));
}
__device__ __forceinline__ void ldsm_x4_t(uint32_t& d0, uint32_t& d1, uint32_t& d2, uint32_t& d3,
                                          uint32_t addr) {
    asm volatile("ldmatrix.sync.aligned.m8n8.x4.trans.shared.b16 {%0,%1,%2,%3}, [%4];"
                 : "=r"(d0), "=r"(d1), "=r"(d2), "=r"(d3) : "r"(addr));
}
__device__ __forceinline__ uint32_t pack_h2(float lo, float hi) {
    __half2 h = __floats2half2_rn(lo, hi);
    return *(uint32_t*)&h;
}
__device__ __forceinline__ uint32_t h2bits(__half2 h) { return *(uint32_t*)&h; }
__device__ __forceinline__ __half2 bits2h2(uint32_t u) { return *(__half2*)&u; }

// ---------------------------------------------------------------------------
// prep: z<4 -> weight transpose+convert; z==4 -> x fp32->fp16
// ---------------------------------------------------------------------------
__global__ void prep(const float* __restrict__ x,
                     const float* __restrict__ W0, const float* __restrict__ W1,
                     const float* __restrict__ W2, const float* __restrict__ W3)
{
    if (blockIdx.z < 4) {
        __shared__ float t[32][33];
        const float* W = (blockIdx.z == 0) ? W0 : (blockIdx.z == 1) ? W1
                       : (blockIdx.z == 2) ? W2 : W3;
        __half* Wt = g_WTh + (size_t)blockIdx.z * 1024 * 1024;
        int bx = blockIdx.x * 32, by = blockIdx.y * 32;
        int tx = threadIdx.x, ty = threadIdx.y;
        #pragma unroll
        for (int i = 0; i < 32; i += 8)
            t[ty + i][tx] = W[(size_t)(by + ty + i) * 1024 + bx + tx];
        __syncthreads();
        #pragma unroll
        for (int i = 0; i < 32; i += 8)
            Wt[(size_t)(bx + ty + i) * 1024 + by + tx] = __float2half(t[tx][ty + i]);
    } else {
        const int tid = threadIdx.y * 32 + threadIdx.x;
        size_t base = (((size_t)blockIdx.y * 32 + blockIdx.x) * 256 + tid) * 16;
        #pragma unroll
        for (int j = 0; j < 4; j++) {
            float4 v = *(const float4*)(x + base + j * 4);
            *(uint32_t*)&g_xh[base + j * 4]     = pack_h2(v.x, v.y);
            *(uint32_t*)&g_xh[base + j * 4 + 2] = pack_h2(v.z, v.w);
        }
    }
}

// ---------------------------------------------------------------------------
// fp16 GEMM (m16n8k16) — k-slab 32, GST 40, ldmatrix frags (unchanged).
// ---------------------------------------------------------------------------
#define GST 40
#define GBUFH (2 * 128 * GST)
#define GSMEM_BYTES (2 * GBUFH * 2)              // 40960 B

__global__ __launch_bounds__(256)
void gemm_h(const float* __restrict__ bias0, const float* __restrict__ bias1,
            const float* __restrict__ bias2, float* __restrict__ Cout, int mode)
{
    extern __shared__ __half smh[];
    const uint32_t sb = smem_u32(smh);
    const int tid = threadIdx.x, lane = tid & 31;
    const int wid = tid >> 5;
    const int wm = wid & 3, wn = wid >> 2;
    const int r = lane >> 2, c = lane & 3;
    const int kmat = lane >> 3, krow = lane & 7;

    int mat, bn;
    const float* bias;
    if (mode == 0) {
        mat = blockIdx.x >> 3;
        bn = (blockIdx.x & 7) * 128;
        bias = (mat == 0) ? bias0 : (mat == 1) ? bias1 : bias2;
    } else {
        mat = 3;
        bn = blockIdx.x * 128;
        bias = bias0;
    }
    const int bm = blockIdx.y * 128;
    const __half* Ah = (mode == 0) ? g_xh : g_ctxh;
    const __half* Bh = g_WTh + (size_t)mat * 1024 * 1024;

    const int row = tid >> 1;
    const int off = (tid & 1) * 16;

    const __half* Ag0 = Ah + (size_t)(bm + row) * 1024 + off;
    const __half* Bg0 = Bh + (size_t)(bn + row) * 1024 + off;

    {
        uint32_t ad = sb + (uint32_t)(row * GST + off) * 2;
        uint32_t bd = sb + (uint32_t)(128 * GST + row * GST + off) * 2;
        cp_async16(ad, Ag0);       cp_async16(ad + 16, Ag0 + 8);
        cp_async16(bd, Bg0);       cp_async16(bd + 16, Bg0 + 8);
        cp_commit();
    }

    float acc[2][8][4];
    #pragma unroll
    for (int im = 0; im < 2; im++)
        #pragma unroll
        for (int nt = 0; nt < 8; nt++)
            #pragma unroll
            for (int j = 0; j < 4; j++) acc[im][nt][j] = 0.f;

    for (int s = 0; s < 32; s++) {
        if (s < 31) {
            const int buf = (s + 1) & 1;
            const int k0 = (s + 1) * 32;
            uint32_t ad = sb + (uint32_t)(buf * GBUFH + row * GST + off) * 2;
            uint32_t bd = sb + (uint32_t)(buf * GBUFH + 128 * GST + row * GST + off) * 2;
            cp_async16(ad, Ag0 + k0);       cp_async16(ad + 16, Ag0 + k0 + 8);
            cp_async16(bd, Bg0 + k0);       cp_async16(bd + 16, Bg0 + k0 + 8);
        }
        cp_commit();
        cp_wait1();
        __syncthreads();

        const uint32_t abase = sb + (uint32_t)((s & 1) * GBUFH) * 2;
        const uint32_t bbase = abase + (uint32_t)(128 * GST) * 2;
        #pragma unroll
        for (int ks = 0; ks < 2; ks++) {
            uint32_t af[2][4];
            #pragma unroll
            for (int im = 0; im < 2; im++) {
                const int arow = wm * 32 + im * 16 + (kmat & 1) * 8 + krow;
                const int acol = ks * 16 + (kmat >> 1) * 8;
                ldsm_x4(af[im][0], af[im][1], af[im][2], af[im][3],
                        abase + (uint32_t)(arow * GST + acol) * 2);
            }
            uint32_t bf[8][2];
            #pragma unroll
            for (int ntp = 0; ntp < 4; ntp++) {
                const int brow = wn * 64 + ntp * 16 + ((kmat >> 1) & 1) * 8 + krow;
                const int bcol = ks * 16 + (kmat & 1) * 8;
                uint32_t d0, d1, d2, d3;
                ldsm_x4(d0, d1, d2, d3, bbase + (uint32_t)(brow * GST + bcol) * 2);
                bf[2 * ntp][0] = d0;  bf[2 * ntp][1] = d1;
                bf[2 * ntp + 1][0] = d2;  bf[2 * ntp + 1][1] = d3;
            }
            #pragma unroll
            for (int nt = 0; nt < 8; nt++) {
                mma_f16(acc[0][nt], af[0], bf[nt]);
                mma_f16(acc[1][nt], af[1], bf[nt]);
            }
        }
        __syncthreads();
    }

    #pragma unroll
    for (int im = 0; im < 2; im++) {
        #pragma unroll
        for (int nt = 0; nt < 8; nt++) {
            const int m = bm + wm * 32 + im * 16 + r;
            const int n = bn + wn * 64 + nt * 8 + 2 * c;
            float2 bz = *(const float2*)&bias[n];
            float v00 = acc[im][nt][0] + bz.x, v01 = acc[im][nt][1] + bz.y;
            float v10 = acc[im][nt][2] + bz.x, v11 = acc[im][nt][3] + bz.y;
            if (mode == 0) {
                const int bb = m >> 10, ss = m & 1023;
                const int hh = n >> 6, dd = n & 63;
                __half* dst = ((mat == 0) ? g_Qh : (mat == 1) ? g_Kh : g_Vh)
                            + ((size_t)((bb * NH + hh) * SEQ + ss)) * DK + dd;
                *(uint32_t*)dst = pack_h2(v00, v01);
                *(uint32_t*)(dst + 8 * DK) = pack_h2(v10, v11);
            } else {
                float* dst = Cout + (size_t)m * 1024 + n;
                float2 a0 = { v00, v01 }, a1 = { v10, v11 };
                *(float2*)dst = a0;
                *(float2*)(dst + 8 * 1024) = a1;
            }
        }
    }
}

// ---------------------------------------------------------------------------
// Geometry bias (fp16, mask folded, pre-scaled by log2e for exp2 softmax)
// ---------------------------------------------------------------------------
__global__ __launch_bounds__(256)
void geom_bias_kernel(const float* __restrict__ geom, const float* __restrict__ Wg,
                      const float* __restrict__ bg, const int* __restrict__ mask)
{
    __shared__ float wgs[7][16];
    __shared__ float bgs[16];
    int tid = threadIdx.x;
    if (tid < 112) wgs[tid / 16][tid % 16] = Wg[tid] * LOG2E;
    if (tid < 16)  bgs[tid] = bg[tid] * LOG2E;
    __syncthreads();

    size_t idx = (size_t)blockIdx.x * 256 + tid;
    const int k2 = (int)(idx & 511);
    const int q  = (int)((idx >> 9) & 1023);
    const int b  = (int)(idx >> 19);
    const int k  = 2 * k2;

    const float2* gp = (const float2*)(geom + ((size_t)(b * 1024 + q) * 1024 + k) * 7);
    float2 t[7];
    #pragma unroll
    for (int i = 0; i < 7; i++) t[i] = gp[i];
    float ga[7], gb[7];
    ga[0]=t[0].x; ga[1]=t[0].y; ga[2]=t[1].x; ga[3]=t[1].y; ga[4]=t[2].x; ga[5]=t[2].y; ga[6]=t[3].x;
    gb[0]=t[3].y; gb[1]=t[4].x; gb[2]=t[4].y; gb[3]=t[5].x; gb[4]=t[5].y; gb[5]=t[6].x; gb[6]=t[6].y;

    const bool live0 = mask[b * SEQ + k] != 0;
    const bool live1 = mask[b * SEQ + k + 1] != 0;
    __half2* outp = (__half2*)(g_biash + ((size_t)(b * NH) * SEQ + q) * SEQ + k);

    #pragma unroll
    for (int h = 0; h < NH; h++) {
        float va = bgs[h], vb = bgs[h];
        #pragma unroll
        for (int i = 0; i < 7; i++) {
            va += ga[i] * wgs[i][h];
            vb += gb[i] * wgs[i][h];
        }
        __half2 o = __floats2half2_rn(live0 ? va : -43000.f, live1 ? vb : -43000.f);
        outp[(size_t)h * (SEQ * SEQ / 2)] = o;
    }
}

// ---------------------------------------------------------------------------
// fp16 flash attention v4: occupancy 4 -> single wave (512 CTAs <= 592 slots).
// Fused per-k-octet S->softmax->PV (hS 4 live regs), bias direct from gmem,
// K/V double-buffered cp.async with race-free wait0->sync->prefetch order.
// ---------------------------------------------------------------------------
#define AVS 72
#define KTH (64 * AVS)
#define AOFF_K(buf) ((buf) * KTH)
#define AOFF_V(buf) (2 * KTH + (buf) * KTH)
#define ASMEM_BYTES (4 * KTH * 2)                  // 36864 B
#define ONES_H2 0x3C003C00u

__global__ __launch_bounds__(256, 4)
void attn_h()
{
    extern __shared__ __half smh[];
    const uint32_t sb = smem_u32(smh);

    const int qb = blockIdx.x * 128;
    const int h  = blockIdx.y;
    const int b  = blockIdx.z;
    const __half* Qp = g_Qh + (size_t)((b * NH + h) * SEQ) * DK;
    const __half* Kp = g_Kh + (size_t)((b * NH + h) * SEQ) * DK;
    const __half* Vp = g_Vh + (size_t)((b * NH + h) * SEQ) * DK;
    const __half* Bp = g_biash + (size_t)(b * NH + h) * SEQ * SEQ;

    const int tid = threadIdx.x;
    const int lane = tid & 31, wid = tid >> 5;
    const int r = lane >> 2, c = lane & 3;
    const int q0 = wid * 16;

    const int rkv  = tid >> 2;
    const int okv  = (tid & 3) * 16;

    uint32_t qf[4][4];
    {
        const __half* qr0 = Qp + (size_t)(qb + q0 + r) * DK;
        const __half* qr1 = Qp + (size_t)(qb + q0 + r + 8) * DK;
        #pragma unroll
        for (int ks = 0; ks < 4; ks++) {
            qf[ks][0] = *(const uint32_t*)&qr0[ks * 16 + 2 * c];
            qf[ks][1] = *(const uint32_t*)&qr1[ks * 16 + 2 * c];
            qf[ks][2] = *(const uint32_t*)&qr0[ks * 16 + 2 * c + 8];
            qf[ks][3] = *(const uint32_t*)&qr1[ks * 16 + 2 * c + 8];
        }
    }

    // prologue: K/V tile 0
    {
        const __half* Kg = Kp + (size_t)rkv * DK + okv;
        const __half* Vg = Vp + (size_t)rkv * DK + okv;
        uint32_t kd = sb + (uint32_t)(AOFF_K(0) + rkv * AVS + okv) * 2;
        uint32_t vd = sb + (uint32_t)(AOFF_V(0) + rkv * AVS + okv) * 2;
        cp_async16(kd, Kg);       cp_async16(kd + 16, Kg + 8);
        cp_async16(vd, Vg);       cp_async16(vd + 16, Vg + 8);
        cp_commit();
    }

    float oAcc[8][4];
    #pragma unroll
    for (int dt = 0; dt < 8; dt++)
        #pragma unroll
        for (int j = 0; j < 4; j++) oAcc[dt][j] = 0.f;
    float lAcc[4] = { 0.f, 0.f, 0.f, 0.f };

    const __half2 SC2 = __float2half2_rn(0.125f * LOG2E);
    const int kmat = lane >> 3;
    const int krow_in = lane & 7;

    for (int kt = 0; kt < 16; kt++) {
        cp_wait0();            // tile kt fully landed
        __syncthreads();       // all warps done reading buf (kt-1)&1 == (kt+1)&1
        if (kt < 15) {         // safe to overwrite it now
            const int buf = (kt + 1) & 1;
            const int kb2 = (kt + 1) * 64;
            const __half* Kg = Kp + (size_t)(kb2 + rkv) * DK + okv;
            const __half* Vg = Vp + (size_t)(kb2 + rkv) * DK + okv;
            uint32_t kd = sb + (uint32_t)(AOFF_K(buf) + rkv * AVS + okv) * 2;
            uint32_t vd = sb + (uint32_t)(AOFF_V(buf) + rkv * AVS + okv) * 2;
            cp_async16(kd, Kg);       cp_async16(kd + 16, Kg + 8);
            cp_async16(vd, Vg);       cp_async16(vd + 16, Vg + 8);
            cp_commit();
        }

        const int buf = kt & 1;
        const uint32_t kbase = sb + (uint32_t)AOFF_K(buf) * 2;
        const uint32_t vbase = sb + (uint32_t)AOFF_V(buf) * 2;
        const __half* Bg = Bp + (size_t)(qb + q0 + r) * SEQ + kt * 64;

        const uint32_t ones[2] = { ONES_H2, ONES_H2 };

        // fused per-k-octet-pair: S-mma -> scale+bias -> exp2 -> l-mma -> PV
        #pragma unroll
        for (int ntp = 0; ntp < 4; ntp++) {
            uint32_t hsA[2] = { 0u, 0u };
            uint32_t hsB[2] = { 0u, 0u };
            {
                const int seqrow = ntp * 16 + ((kmat >> 1) & 1) * 8 + krow_in;
                #pragma unroll
                for (int dk = 0; dk < 4; dk++) {
                    const int col = dk * 16 + (kmat & 1) * 8;
                    uint32_t addr = kbase + (uint32_t)(seqrow * AVS + col) * 2;
                    uint32_t d0, d1, d2, d3;
                    ldsm_x4(d0, d1, d2, d3, addr);
                    uint32_t b01[2] = { d0, d1 };
                    uint32_t b23[2] = { d2, d3 };
                    mma_f16c(hsA, qf[dk], b01);
                    mma_f16c(hsB, qf[dk], b23);
                }
            }
            // bias direct from gmem (mask pre-folded, *log2e)
            const int colA = ntp * 16 + 2 * c;
            uint32_t bA0 = *(const uint32_t*)(Bg + colA);
            uint32_t bA1 = *(const uint32_t*)(Bg + 8 * SEQ + colA);
            uint32_t bB0 = *(const uint32_t*)(Bg + colA + 8);
            uint32_t bB1 = *(const uint32_t*)(Bg + 8 * SEQ + colA + 8);
            uint32_t pa[4];
            pa[0] = h2bits(h2exp2(__hfma2(bits2h2(hsA[0]), SC2, bits2h2(bA0))));
            pa[1] = h2bits(h2exp2(__hfma2(bits2h2(hsA[1]), SC2, bits2h2(bA1))));
            pa[2] = h2bits(h2exp2(__hfma2(bits2h2(hsB[0]), SC2, bits2h2(bB0))));
            pa[3] = h2bits(h2exp2(__hfma2(bits2h2(hsB[1]), SC2, bits2h2(bB1))));

            mma_f16(lAcc, pa, ones);              // exact fp32 row-sum of fp16 P
            #pragma unroll
            for (int dtp = 0; dtp < 4; dtp++) {
                const int vrow = ntp * 16 + (kmat & 1) * 8 + krow_in;
                const int vcol = dtp * 16 + ((kmat >> 1) & 1) * 8;
                uint32_t addr = vbase + (uint32_t)(vrow * AVS + vcol) * 2;
                uint32_t d0, d1, d2, d3;
                ldsm_x4_t(d0, d1, d2, d3, addr);
                uint32_t b01[2] = { d0, d1 };
                uint32_t b23[2] = { d2, d3 };
                mma_f16(oAcc[2 * dtp],     pa, b01);
                mma_f16(oAcc[2 * dtp + 1], pa, b23);
            }
        }
    }

    const float iA = 1.f / lAcc[0];
    const float iB = 1.f / lAcc[2];
    __half* Op0 = g_ctxh + (size_t)(b * SEQ + qb + q0 + r) * DMODEL + h * 64 + 2 * c;
    __half* Op1 = Op0 + (size_t)8 * DMODEL;
    #pragma unroll
    for (int dt = 0; dt < 8; dt++) {
        *(uint32_t*)(Op0 + dt * 8) = pack_h2(oAcc[dt][0] * iA, oAcc[dt][1] * iA);
        *(uint32_t*)(Op1 + dt * 8) = pack_h2(oAcc[dt][2] * iB, oAcc[dt][3] * iB);
    }
}

// ---------------------------------------------------------------------------
extern "C" void kernel_launch(void* const* d_in, const int* in_sizes, int n_in,
                              void* d_out, int out_size)
{
    const float* x    = (const float*)d_in[0];
    const float* geom = (const float*)d_in[1];
    const int*   mask = (const int*)d_in[2];
    const float* Wq = (const float*)d_in[3];
    const float* bq = (const float*)d_in[4];
    const float* Wk = (const float*)d_in[5];
    const float* bk = (const float*)d_in[6];
    const float* Wv = (const float*)d_in[7];
    const float* bv = (const float*)d_in[8];
    const float* Wo = (const float*)d_in[9];
    const float* bo = (const float*)d_in[10];
    const float* Wg = (const float*)d_in[11];
    const float* bg = (const float*)d_in[12];
    float* out = (float*)d_out;

    cudaFuncSetAttribute(gemm_h, cudaFuncAttributeMaxDynamicSharedMemorySize, GSMEM_BYTES);
    cudaFuncSetAttribute(attn_h, cudaFuncAttributeMaxDynamicSharedMemorySize, ASMEM_BYTES);

    prep<<<dim3(32, 32, 5), dim3(32, 8)>>>(x, Wq, Wk, Wv, Wo);

    gemm_h<<<dim3(24, 32), 256, GSMEM_BYTES>>>(bq, bk, bv, nullptr, 0);

    geom_bias_kernel<<<(BATCH * SEQ * SEQ / 2) / 256, 256>>>(geom, Wg, bg, mask);

    attn_h<<<dim3(SEQ / 128, NH, BATCH), 256, ASMEM_BYTES>>>();     // profiled slot

    gemm_h<<<dim3(8, 32), 256, GSMEM_BYTES>>>(bo, nullptr, nullptr, out, 1);
}

// round 14
// speedup vs baseline: 1.2873x; 1.2873x over previous
#include <cuda_runtime.h>
#include <cuda_fp16.h>
#include <math.h>
#include <cstdint>

#define BATCH  4
#define SEQ    1024
#define DMODEL 1024
#define NH     16
#define DK     64
#define LOG2E  1.4426950408889634f

// ---------------- scratch (device globals: allocation-free) ----------------
__device__ __half g_xh[BATCH * SEQ * DMODEL];
__device__ __half g_WTh[4 * 1024 * 1024];     // W^T per matrix: [n][k] fp16
__device__ __half g_Qh[BATCH * NH * SEQ * DK];
__device__ __half g_Kh[BATCH * NH * SEQ * DK];
__device__ __half g_Vh[BATCH * NH * SEQ * DK];
__device__ __half g_ctxh[BATCH * SEQ * DMODEL];
__device__ __half g_biash[(size_t)BATCH * NH * SEQ * SEQ];  // bias*log2e, mask folded

// ---------------- helpers ----------------
__device__ __forceinline__ void mma_f16(float c[4], const uint32_t a[4], const uint32_t b[2]) {
    asm volatile("mma.sync.aligned.m16n8k16.row.col.f32.f16.f16.f32 "
                 "{%0,%1,%2,%3}, {%4,%5,%6,%7}, {%8,%9}, {%0,%1,%2,%3};"
                 : "+f"(c[0]), "+f"(c[1]), "+f"(c[2]), "+f"(c[3])
                 : "r"(a[0]), "r"(a[1]), "r"(a[2]), "r"(a[3]), "r"(b[0]), "r"(b[1]));
}
__device__ __forceinline__ uint32_t smem_u32(const void* p) {
    uint32_t a;
    asm("{ .reg .u64 t; cvta.to.shared.u64 t, %1; cvt.u32.u64 %0, t; }" : "=r"(a) : "l"(p));
    return a;
}
__device__ __forceinline__ void cp_async16(uint32_t s, const void* g) {
    asm volatile("cp.async.cg.shared.global [%0], [%1], 16;" :: "r"(s), "l"(g) : "memory");
}
__device__ __forceinline__ void cp_commit() {
    asm volatile("cp.async.commit_group;" ::: "memory");
}
__device__ __forceinline__ void cp_wait1() {
    asm volatile("cp.async.wait_group 1;" ::: "memory");
}
__device__ __forceinline__ void ldsm_x4(uint32_t& d0, uint32_t& d1, uint32_t& d2, uint32_t& d3,
                                        uint32_t addr) {
    asm volatile("ldmatrix.sync.aligned.m8n8.x4.shared.b16 {%0,%1,%2,%3}, [%4];"
                 : "=r"(d0), "=r"(d1), "=r"(d2), "=r"(d3) : "r"(addr));
}
__device__ __forceinline__ void ldsm_x4_t(uint32_t& d0, uint32_t& d1, uint32_t& d2, uint32_t& d3,
                                          uint32_t addr) {
    asm volatile("ldmatrix.sync.aligned.m8n8.x4.trans.shared.b16 {%0,%1,%2,%3}, [%4];"
                 : "=r"(d0), "=r"(d1), "=r"(d2), "=r"(d3) : "r"(addr));
}
__device__ __forceinline__ uint32_t pack_h2(float lo, float hi) {
    __half2 h = __floats2half2_rn(lo, hi);
    return *(uint32_t*)&h;
}
__device__ __forceinline__ uint32_t h2bits(__half2 h) { return *(uint32_t*)&h; }
__device__ __forceinline__ __half2 bits2h2(uint32_t u) { return *(__half2*)&u; }

// ---------------------------------------------------------------------------
// prep: z<4 -> weight transpose+convert; z==4 -> x fp32->fp16
// ---------------------------------------------------------------------------
__global__ void prep(const float* __restrict__ x,
                     const float* __restrict__ W0, const float* __restrict__ W1,
                     const float* __restrict__ W2, const float* __restrict__ W3)
{
    if (blockIdx.z < 4) {
        __shared__ float t[32][33];
        const float* W = (blockIdx.z == 0) ? W0 : (blockIdx.z == 1) ? W1
                       : (blockIdx.z == 2) ? W2 : W3;
        __half* Wt = g_WTh + (size_t)blockIdx.z * 1024 * 1024;
        int bx = blockIdx.x * 32, by = blockIdx.y * 32;
        int tx = threadIdx.x, ty = threadIdx.y;
        #pragma unroll
        for (int i = 0; i < 32; i += 8)
            t[ty + i][tx] = W[(size_t)(by + ty + i) * 1024 + bx + tx];
        __syncthreads();
        #pragma unroll
        for (int i = 0; i < 32; i += 8)
            Wt[(size_t)(bx + ty + i) * 1024 + by + tx] = __float2half(t[tx][ty + i]);
    } else {
        const int tid = threadIdx.y * 32 + threadIdx.x;
        size_t base = (((size_t)blockIdx.y * 32 + blockIdx.x) * 256 + tid) * 16;
        #pragma unroll
        for (int j = 0; j < 4; j++) {
            float4 v = *(const float4*)(x + base + j * 4);
            *(uint32_t*)&g_xh[base + j * 4]     = pack_h2(v.x, v.y);
            *(uint32_t*)&g_xh[base + j * 4 + 2] = pack_h2(v.z, v.w);
        }
    }
}

// ---------------------------------------------------------------------------
// fp16 GEMM (m16n8k16) — k-slab 32, GST 40, ldmatrix frags (unchanged).
// ---------------------------------------------------------------------------
#define GST 40
#define GBUFH (2 * 128 * GST)
#define GSMEM_BYTES (2 * GBUFH * 2)              // 40960 B

__global__ __launch_bounds__(256)
void gemm_h(const float* __restrict__ bias0, const float* __restrict__ bias1,
            const float* __restrict__ bias2, float* __restrict__ Cout, int mode)
{
    extern __shared__ __half smh[];
    const uint32_t sb = smem_u32(smh);
    const int tid = threadIdx.x, lane = tid & 31;
    const int wid = tid >> 5;
    const int wm = wid & 3, wn = wid >> 2;
    const int r = lane >> 2, c = lane & 3;
    const int kmat = lane >> 3, krow = lane & 7;

    int mat, bn;
    const float* bias;
    if (mode == 0) {
        mat = blockIdx.x >> 3;
        bn = (blockIdx.x & 7) * 128;
        bias = (mat == 0) ? bias0 : (mat == 1) ? bias1 : bias2;
    } else {
        mat = 3;
        bn = blockIdx.x * 128;
        bias = bias0;
    }
    const int bm = blockIdx.y * 128;
    const __half* Ah = (mode == 0) ? g_xh : g_ctxh;
    const __half* Bh = g_WTh + (size_t)mat * 1024 * 1024;

    const int row = tid >> 1;
    const int off = (tid & 1) * 16;

    const __half* Ag0 = Ah + (size_t)(bm + row) * 1024 + off;
    const __half* Bg0 = Bh + (size_t)(bn + row) * 1024 + off;

    {
        uint32_t ad = sb + (uint32_t)(row * GST + off) * 2;
        uint32_t bd = sb + (uint32_t)(128 * GST + row * GST + off) * 2;
        cp_async16(ad, Ag0);       cp_async16(ad + 16, Ag0 + 8);
        cp_async16(bd, Bg0);       cp_async16(bd + 16, Bg0 + 8);
        cp_commit();
    }

    float acc[2][8][4];
    #pragma unroll
    for (int im = 0; im < 2; im++)
        #pragma unroll
        for (int nt = 0; nt < 8; nt++)
            #pragma unroll
            for (int j = 0; j < 4; j++) acc[im][nt][j] = 0.f;

    for (int s = 0; s < 32; s++) {
        if (s < 31) {
            const int buf = (s + 1) & 1;
            const int k0 = (s + 1) * 32;
            uint32_t ad = sb + (uint32_t)(buf * GBUFH + row * GST + off) * 2;
            uint32_t bd = sb + (uint32_t)(buf * GBUFH + 128 * GST + row * GST + off) * 2;
            cp_async16(ad, Ag0 + k0);       cp_async16(ad + 16, Ag0 + k0 + 8);
            cp_async16(bd, Bg0 + k0);       cp_async16(bd + 16, Bg0 + k0 + 8);
        }
        cp_commit();
        cp_wait1();
        __syncthreads();

        const uint32_t abase = sb + (uint32_t)((s & 1) * GBUFH) * 2;
        const uint32_t bbase = abase + (uint32_t)(128 * GST) * 2;
        #pragma unroll
        for (int ks = 0; ks < 2; ks++) {
            uint32_t af[2][4];
            #pragma unroll
            for (int im = 0; im < 2; im++) {
                const int arow = wm * 32 + im * 16 + (kmat & 1) * 8 + krow;
                const int acol = ks * 16 + (kmat >> 1) * 8;
                ldsm_x4(af[im][0], af[im][1], af[im][2], af[im][3],
                        abase + (uint32_t)(arow * GST + acol) * 2);
            }
            uint32_t bf[8][2];
            #pragma unroll
            for (int ntp = 0; ntp < 4; ntp++) {
                const int brow = wn * 64 + ntp * 16 + ((kmat >> 1) & 1) * 8 + krow;
                const int bcol = ks * 16 + (kmat & 1) * 8;
                uint32_t d0, d1, d2, d3;
                ldsm_x4(d0, d1, d2, d3, bbase + (uint32_t)(brow * GST + bcol) * 2);
                bf[2 * ntp][0] = d0;  bf[2 * ntp][1] = d1;
                bf[2 * ntp + 1][0] = d2;  bf[2 * ntp + 1][1] = d3;
            }
            #pragma unroll
            for (int nt = 0; nt < 8; nt++) {
                mma_f16(acc[0][nt], af[0], bf[nt]);
                mma_f16(acc[1][nt], af[1], bf[nt]);
            }
        }
        __syncthreads();
    }

    #pragma unroll
    for (int im = 0; im < 2; im++) {
        #pragma unroll
        for (int nt = 0; nt < 8; nt++) {
            const int m = bm + wm * 32 + im * 16 + r;
            const int n = bn + wn * 64 + nt * 8 + 2 * c;
            float2 bz = *(const float2*)&bias[n];
            float v00 = acc[im][nt][0] + bz.x, v01 = acc[im][nt][1] + bz.y;
            float v10 = acc[im][nt][2] + bz.x, v11 = acc[im][nt][3] + bz.y;
            if (mode == 0) {
                const int bb = m >> 10, ss = m & 1023;
                const int hh = n >> 6, dd = n & 63;
                __half* dst = ((mat == 0) ? g_Qh : (mat == 1) ? g_Kh : g_Vh)
                            + ((size_t)((bb * NH + hh) * SEQ + ss)) * DK + dd;
                *(uint32_t*)dst = pack_h2(v00, v01);
                *(uint32_t*)(dst + 8 * DK) = pack_h2(v10, v11);
            } else {
                float* dst = Cout + (size_t)m * 1024 + n;
                float2 a0 = { v00, v01 }, a1 = { v10, v11 };
                *(float2*)dst = a0;
                *(float2*)(dst + 8 * 1024) = a1;
            }
        }
    }
}

// ---------------------------------------------------------------------------
// Geometry bias (fp16, mask folded, pre-scaled by log2e for exp2 softmax)
// ---------------------------------------------------------------------------
__global__ __launch_bounds__(256)
void geom_bias_kernel(const float* __restrict__ geom, const float* __restrict__ Wg,
                      const float* __restrict__ bg, const int* __restrict__ mask)
{
    __shared__ float wgs[7][16];
    __shared__ float bgs[16];
    int tid = threadIdx.x;
    if (tid < 112) wgs[tid / 16][tid % 16] = Wg[tid] * LOG2E;
    if (tid < 16)  bgs[tid] = bg[tid] * LOG2E;
    __syncthreads();

    size_t idx = (size_t)blockIdx.x * 256 + tid;
    const int k2 = (int)(idx & 511);
    const int q  = (int)((idx >> 9) & 1023);
    const int b  = (int)(idx >> 19);
    const int k  = 2 * k2;

    const float2* gp = (const float2*)(geom + ((size_t)(b * 1024 + q) * 1024 + k) * 7);
    float2 t[7];
    #pragma unroll
    for (int i = 0; i < 7; i++) t[i] = gp[i];
    float ga[7], gb[7];
    ga[0]=t[0].x; ga[1]=t[0].y; ga[2]=t[1].x; ga[3]=t[1].y; ga[4]=t[2].x; ga[5]=t[2].y; ga[6]=t[3].x;
    gb[0]=t[3].y; gb[1]=t[4].x; gb[2]=t[4].y; gb[3]=t[5].x; gb[4]=t[5].y; gb[5]=t[6].x; gb[6]=t[6].y;

    const bool live0 = mask[b * SEQ + k] != 0;
    const bool live1 = mask[b * SEQ + k + 1] != 0;
    __half2* outp = (__half2*)(g_biash + ((size_t)(b * NH) * SEQ + q) * SEQ + k);

    #pragma unroll
    for (int h = 0; h < NH; h++) {
        float va = bgs[h], vb = bgs[h];
        #pragma unroll
        for (int i = 0; i < 7; i++) {
            va += ga[i] * wgs[i][h];
            vb += gb[i] * wgs[i][h];
        }
        __half2 o = __floats2half2_rn(live0 ? va : -43000.f, live1 ? vb : -43000.f);
        outp[(size_t)h * (SEQ * SEQ / 2)] = o;
    }
}

// ---------------------------------------------------------------------------
// fp16 flash attention (R11 structure): 256 thr / 8 warps, q-tile 128,
// no-max exp2 softmax, fp32 S accumulators, ones-MMA row sum.
// K/V double-buffered cp.async (wait1 pipeline); bias DIRECT from gmem.
// ---------------------------------------------------------------------------
#define AVS 72
#define KTH (64 * AVS)
#define AOFF_K(buf) ((buf) * KTH)
#define AOFF_V(buf) (2 * KTH + (buf) * KTH)
#define ASMEM_BYTES (4 * KTH * 2)                  // 36864 B
#define ONES_H2 0x3C003C00u

__global__ __launch_bounds__(256, 2)
void attn_h()
{
    extern __shared__ __half smh[];
    const uint32_t sb = smem_u32(smh);

    const int qb = blockIdx.x * 128;
    const int h  = blockIdx.y;
    const int b  = blockIdx.z;
    const __half* Qp = g_Qh + (size_t)((b * NH + h) * SEQ) * DK;
    const __half* Kp = g_Kh + (size_t)((b * NH + h) * SEQ) * DK;
    const __half* Vp = g_Vh + (size_t)((b * NH + h) * SEQ) * DK;
    const __half* Bp = g_biash + (size_t)(b * NH + h) * SEQ * SEQ;

    const int tid = threadIdx.x;
    const int lane = tid & 31, wid = tid >> 5;
    const int r = lane >> 2, c = lane & 3;
    const int q0 = wid * 16;

    const int rkv  = tid >> 2;
    const int okv  = (tid & 3) * 16;

    uint32_t qf[4][4];
    {
        const __half* qr0 = Qp + (size_t)(qb + q0 + r) * DK;
        const __half* qr1 = Qp + (size_t)(qb + q0 + r + 8) * DK;
        #pragma unroll
        for (int ks = 0; ks < 4; ks++) {
            qf[ks][0] = *(const uint32_t*)&qr0[ks * 16 + 2 * c];
            qf[ks][1] = *(const uint32_t*)&qr1[ks * 16 + 2 * c];
            qf[ks][2] = *(const uint32_t*)&qr0[ks * 16 + 2 * c + 8];
            qf[ks][3] = *(const uint32_t*)&qr1[ks * 16 + 2 * c + 8];
        }
    }

    // prologue: K/V tile 0
    {
        const __half* Kg = Kp + (size_t)rkv * DK + okv;
        const __half* Vg = Vp + (size_t)rkv * DK + okv;
        uint32_t kd = sb + (uint32_t)(AOFF_K(0) + rkv * AVS + okv) * 2;
        uint32_t vd = sb + (uint32_t)(AOFF_V(0) + rkv * AVS + okv) * 2;
        cp_async16(kd, Kg);       cp_async16(kd + 16, Kg + 8);
        cp_async16(vd, Vg);       cp_async16(vd + 16, Vg + 8);
        cp_commit();
    }

    float oAcc[8][4];
    #pragma unroll
    for (int dt = 0; dt < 8; dt++)
        #pragma unroll
        for (int j = 0; j < 4; j++) oAcc[dt][j] = 0.f;
    float lAcc[4] = { 0.f, 0.f, 0.f, 0.f };

    const float SC = 0.125f * LOG2E;
    const int kmat = lane >> 3;
    const int krow_in = lane & 7;

    for (int kt = 0; kt < 16; kt++) {
        if (kt < 15) {
            const int buf = (kt + 1) & 1;
            const int kb2 = (kt + 1) * 64;
            const __half* Kg = Kp + (size_t)(kb2 + rkv) * DK + okv;
            const __half* Vg = Vp + (size_t)(kb2 + rkv) * DK + okv;
            uint32_t kd = sb + (uint32_t)(AOFF_K(buf) + rkv * AVS + okv) * 2;
            uint32_t vd = sb + (uint32_t)(AOFF_V(buf) + rkv * AVS + okv) * 2;
            cp_async16(kd, Kg);       cp_async16(kd + 16, Kg + 8);
            cp_async16(vd, Vg);       cp_async16(vd + 16, Vg + 8);
        }
        cp_commit();
        cp_wait1();
        __syncthreads();

        const int buf = kt & 1;
        const uint32_t kbase = sb + (uint32_t)AOFF_K(buf) * 2;
        const uint32_t vbase = sb + (uint32_t)AOFF_V(buf) * 2;
        const __half* Bg0 = Bp + (size_t)(qb + q0 + r) * SEQ + kt * 64;
        const __half* Bg1 = Bg0 + (size_t)8 * SEQ;

        float sAcc[8][4];
        #pragma unroll
        for (int nt = 0; nt < 8; nt++)
            #pragma unroll
            for (int j = 0; j < 4; j++) sAcc[nt][j] = 0.f;

        #pragma unroll
        for (int ks = 0; ks < 4; ks++) {
            #pragma unroll
            for (int ntp = 0; ntp < 4; ntp++) {
                const int seqrow = ntp * 16 + ((kmat >> 1) & 1) * 8 + krow_in;
                const int col = ks * 16 + (kmat & 1) * 8;
                uint32_t addr = kbase + (uint32_t)(seqrow * AVS + col) * 2;
                uint32_t d0, d1, d2, d3;
                ldsm_x4(d0, d1, d2, d3, addr);
                uint32_t b01[2] = { d0, d1 };
                uint32_t b23[2] = { d2, d3 };
                mma_f16(sAcc[2 * ntp],     qf[ks], b01);
                mma_f16(sAcc[2 * ntp + 1], qf[ks], b23);
            }
        }

        // ---- P = exp2(s*SC + bias), no max; bias direct from gmem ----
        __half2 hA[8], hB[8];
        #pragma unroll
        for (int nt = 0; nt < 8; nt++) {
            uint32_t uA = *(const uint32_t*)(Bg0 + nt * 8 + 2 * c);
            uint32_t uB = *(const uint32_t*)(Bg1 + nt * 8 + 2 * c);
            float2 bzA = __half22float2(bits2h2(uA));
            float2 bzB = __half22float2(bits2h2(uB));
            hA[nt] = __floats2half2_rn(fmaf(sAcc[nt][0], SC, bzA.x),
                                       fmaf(sAcc[nt][1], SC, bzA.y));
            hB[nt] = __floats2half2_rn(fmaf(sAcc[nt][2], SC, bzB.x),
                                       fmaf(sAcc[nt][3], SC, bzB.y));
        }

        const uint32_t ones[2] = { ONES_H2, ONES_H2 };
        #pragma unroll
        for (int ks = 0; ks < 4; ks++) {
            uint32_t pa[4];
            pa[0] = h2bits(h2exp2(hA[2 * ks]));
            pa[1] = h2bits(h2exp2(hB[2 * ks]));
            pa[2] = h2bits(h2exp2(hA[2 * ks + 1]));
            pa[3] = h2bits(h2exp2(hB[2 * ks + 1]));
            mma_f16(lAcc, pa, ones);                  // exact fp32 row-sum of fp16 P
            #pragma unroll
            for (int dtp = 0; dtp < 4; dtp++) {
                const int vrow = ks * 16 + (kmat & 1) * 8 + krow_in;
                const int vcol = dtp * 16 + ((kmat >> 1) & 1) * 8;
                uint32_t addr = vbase + (uint32_t)(vrow * AVS + vcol) * 2;
                uint32_t d0, d1, d2, d3;
                ldsm_x4_t(d0, d1, d2, d3, addr);
                uint32_t b01[2] = { d0, d1 };
                uint32_t b23[2] = { d2, d3 };
                mma_f16(oAcc[2 * dtp],     pa, b01);
                mma_f16(oAcc[2 * dtp + 1], pa, b23);
            }
        }
        __syncthreads();
    }

    const float iA = 1.f / lAcc[0];
    const float iB = 1.f / lAcc[2];
    __half* Op0 = g_ctxh + (size_t)(b * SEQ + qb + q0 + r) * DMODEL + h * 64 + 2 * c;
    __half* Op1 = Op0 + (size_t)8 * DMODEL;
    #pragma unroll
    for (int dt = 0; dt < 8; dt++) {
        *(uint32_t*)(Op0 + dt * 8) = pack_h2(oAcc[dt][0] * iA, oAcc[dt][1] * iA);
        *(uint32_t*)(Op1 + dt * 8) = pack_h2(oAcc[dt][2] * iB, oAcc[dt][3] * iB);
    }
}

// ---------------------------------------------------------------------------
extern "C" void kernel_launch(void* const* d_in, const int* in_sizes, int n_in,
                              void* d_out, int out_size)
{
    const float* x    = (const float*)d_in[0];
    const float* geom = (const float*)d_in[1];
    const int*   mask = (const int*)d_in[2];
    const float* Wq = (const float*)d_in[3];
    const float* bq = (const float*)d_in[4];
    const float* Wk = (const float*)d_in[5];
    const float* bk = (const float*)d_in[6];
    const float* Wv = (const float*)d_in[7];
    const float* bv = (const float*)d_in[8];
    const float* Wo = (const float*)d_in[9];
    const float* bo = (const float*)d_in[10];
    const float* Wg = (const float*)d_in[11];
    const float* bg = (const float*)d_in[12];
    float* out = (float*)d_out;

    cudaFuncSetAttribute(gemm_h, cudaFuncAttributeMaxDynamicSharedMemorySize, GSMEM_BYTES);
    cudaFuncSetAttribute(attn_h, cudaFuncAttributeMaxDynamicSharedMemorySize, ASMEM_BYTES);

    prep<<<dim3(32, 32, 5), dim3(32, 8)>>>(x, Wq, Wk, Wv, Wo);

    gemm_h<<<dim3(24, 32), 256, GSMEM_BYTES>>>(bq, bk, bv, nullptr, 0);

    geom_bias_kernel<<<(BATCH * SEQ * SEQ / 2) / 256, 256>>>(geom, Wg, bg, mask);

    attn_h<<<dim3(SEQ / 128, NH, BATCH), 256, ASMEM_BYTES>>>();     // profiled slot

    gemm_h<<<dim3(8, 32), 256, GSMEM_BYTES>>>(bo, nullptr, nullptr, out, 1);
}

// round 15
// speedup vs baseline: 1.3539x; 1.0517x over previous
#include <cuda_runtime.h>
#include <cuda_fp16.h>
#include <math.h>
#include <cstdint>

#define BATCH  4
#define SEQ    1024
#define DMODEL 1024
#define NH     16
#define DK     64
#define LOG2E  1.4426950408889634f

// ---------------- scratch (device globals: allocation-free) ----------------
__device__ __half g_xh[BATCH * SEQ * DMODEL];
__device__ __half g_WTh[4 * 1024 * 1024];     // W^T per matrix: [n][k] fp16
__device__ __half g_Qh[BATCH * NH * SEQ * DK];
__device__ __half g_Kh[BATCH * NH * SEQ * DK];
__device__ __half g_Vh[BATCH * NH * SEQ * DK];
__device__ __half g_ctxh[BATCH * SEQ * DMODEL];
__device__ __half g_biash[(size_t)BATCH * NH * SEQ * SEQ];  // bias*log2e, mask folded

// ---------------- helpers ----------------
__device__ __forceinline__ void mma_f16(float c[4], const uint32_t a[4], const uint32_t b[2]) {
    asm volatile("mma.sync.aligned.m16n8k16.row.col.f32.f16.f16.f32 "
                 "{%0,%1,%2,%3}, {%4,%5,%6,%7}, {%8,%9}, {%0,%1,%2,%3};"
                 : "+f"(c[0]), "+f"(c[1]), "+f"(c[2]), "+f"(c[3])
                 : "r"(a[0]), "r"(a[1]), "r"(a[2]), "r"(a[3]), "r"(b[0]), "r"(b[1]));
}
__device__ __forceinline__ uint32_t smem_u32(const void* p) {
    uint32_t a;
    asm("{ .reg .u64 t; cvta.to.shared.u64 t, %1; cvt.u32.u64 %0, t; }" : "=r"(a) : "l"(p));
    return a;
}
__device__ __forceinline__ void cp_async16(uint32_t s, const void* g) {
    asm volatile("cp.async.cg.shared.global [%0], [%1], 16;" :: "r"(s), "l"(g) : "memory");
}
__device__ __forceinline__ void cp_commit() {
    asm volatile("cp.async.commit_group;" ::: "memory");
}
__device__ __forceinline__ void cp_wait1() {
    asm volatile("cp.async.wait_group 1;" ::: "memory");
}
__device__ __forceinline__ void ldsm_x4(uint32_t& d0, uint32_t& d1, uint32_t& d2, uint32_t& d3,
                                        uint32_t addr) {
    asm volatile("ldmatrix.sync.aligned.m8n8.x4.shared.b16 {%0,%1,%2,%3}, [%4];"
                 : "=r"(d0), "=r"(d1), "=r"(d2), "=r"(d3) : "r"(addr));
}
__device__ __forceinline__ void ldsm_x4_t(uint32_t& d0, uint32_t& d1, uint32_t& d2, uint32_t& d3,
                                          uint32_t addr) {
    asm volatile("ldmatrix.sync.aligned.m8n8.x4.trans.shared.b16 {%0,%1,%2,%3}, [%4];"
                 : "=r"(d0), "=r"(d1), "=r"(d2), "=r"(d3) : "r"(addr));
}
__device__ __forceinline__ uint32_t pack_h2(float lo, float hi) {
    __half2 h = __floats2half2_rn(lo, hi);
    return *(uint32_t*)&h;
}
__device__ __forceinline__ uint32_t h2bits(__half2 h) { return *(uint32_t*)&h; }
__device__ __forceinline__ __half2 bits2h2(uint32_t u) { return *(__half2*)&u; }

// ---------------------------------------------------------------------------
// prep: z<4 -> weight transpose+convert; z==4 -> x fp32->fp16
// ---------------------------------------------------------------------------
__global__ void prep(const float* __restrict__ x,
                     const float* __restrict__ W0, const float* __restrict__ W1,
                     const float* __restrict__ W2, const float* __restrict__ W3)
{
    if (blockIdx.z < 4) {
        __shared__ float t[32][33];
        const float* W = (blockIdx.z == 0) ? W0 : (blockIdx.z == 1) ? W1
                       : (blockIdx.z == 2) ? W2 : W3;
        __half* Wt = g_WTh + (size_t)blockIdx.z * 1024 * 1024;
        int bx = blockIdx.x * 32, by = blockIdx.y * 32;
        int tx = threadIdx.x, ty = threadIdx.y;
        #pragma unroll
        for (int i = 0; i < 32; i += 8)
            t[ty + i][tx] = W[(size_t)(by + ty + i) * 1024 + bx + tx];
        __syncthreads();
        #pragma unroll
        for (int i = 0; i < 32; i += 8)
            Wt[(size_t)(bx + ty + i) * 1024 + by + tx] = __float2half(t[tx][ty + i]);
    } else {
        const int tid = threadIdx.y * 32 + threadIdx.x;
        size_t base = (((size_t)blockIdx.y * 32 + blockIdx.x) * 256 + tid) * 16;
        #pragma unroll
        for (int j = 0; j < 4; j++) {
            float4 v = *(const float4*)(x + base + j * 4);
            *(uint32_t*)&g_xh[base + j * 4]     = pack_h2(v.x, v.y);
            *(uint32_t*)&g_xh[base + j * 4 + 2] = pack_h2(v.z, v.w);
        }
    }
}

// ---------------------------------------------------------------------------
// GEMM body (m16n8k16, k-slab 32, GST 40) as an inlineable device function.
// mode 0: QKV (mat 0..2), mode 1: outproj -> fp32 Cout.
// ---------------------------------------------------------------------------
#define GST 40
#define GBUFH (2 * 128 * GST)
#define GSMEM_BYTES (2 * GBUFH * 2)              // 40960 B

__device__ __forceinline__ void gemm_body(
    __half* smh, int bxg, int byg,
    const float* bias0, const float* bias1, const float* bias2,
    float* Cout, int mode)
{
    const uint32_t sb = smem_u32(smh);
    const int tid = threadIdx.x, lane = tid & 31;
    const int wid = tid >> 5;
    const int wm = wid & 3, wn = wid >> 2;
    const int r = lane >> 2, c = lane & 3;
    const int kmat = lane >> 3, krow = lane & 7;

    int mat, bn;
    const float* bias;
    if (mode == 0) {
        mat = bxg >> 3;
        bn = (bxg & 7) * 128;
        bias = (mat == 0) ? bias0 : (mat == 1) ? bias1 : bias2;
    } else {
        mat = 3;
        bn = bxg * 128;
        bias = bias0;
    }
    const int bm = byg * 128;
    const __half* Ah = (mode == 0) ? g_xh : g_ctxh;
    const __half* Bh = g_WTh + (size_t)mat * 1024 * 1024;

    const int row = tid >> 1;
    const int off = (tid & 1) * 16;

    const __half* Ag0 = Ah + (size_t)(bm + row) * 1024 + off;
    const __half* Bg0 = Bh + (size_t)(bn + row) * 1024 + off;

    {
        uint32_t ad = sb + (uint32_t)(row * GST + off) * 2;
        uint32_t bd = sb + (uint32_t)(128 * GST + row * GST + off) * 2;
        cp_async16(ad, Ag0);       cp_async16(ad + 16, Ag0 + 8);
        cp_async16(bd, Bg0);       cp_async16(bd + 16, Bg0 + 8);
        cp_commit();
    }

    float acc[2][8][4];
    #pragma unroll
    for (int im = 0; im < 2; im++)
        #pragma unroll
        for (int nt = 0; nt < 8; nt++)
            #pragma unroll
            for (int j = 0; j < 4; j++) acc[im][nt][j] = 0.f;

    for (int s = 0; s < 32; s++) {
        if (s < 31) {
            const int buf = (s + 1) & 1;
            const int k0 = (s + 1) * 32;
            uint32_t ad = sb + (uint32_t)(buf * GBUFH + row * GST + off) * 2;
            uint32_t bd = sb + (uint32_t)(buf * GBUFH + 128 * GST + row * GST + off) * 2;
            cp_async16(ad, Ag0 + k0);       cp_async16(ad + 16, Ag0 + k0 + 8);
            cp_async16(bd, Bg0 + k0);       cp_async16(bd + 16, Bg0 + k0 + 8);
        }
        cp_commit();
        cp_wait1();
        __syncthreads();

        const uint32_t abase = sb + (uint32_t)((s & 1) * GBUFH) * 2;
        const uint32_t bbase = abase + (uint32_t)(128 * GST) * 2;
        #pragma unroll
        for (int ks = 0; ks < 2; ks++) {
            uint32_t af[2][4];
            #pragma unroll
            for (int im = 0; im < 2; im++) {
                const int arow = wm * 32 + im * 16 + (kmat & 1) * 8 + krow;
                const int acol = ks * 16 + (kmat >> 1) * 8;
                ldsm_x4(af[im][0], af[im][1], af[im][2], af[im][3],
                        abase + (uint32_t)(arow * GST + acol) * 2);
            }
            uint32_t bf[8][2];
            #pragma unroll
            for (int ntp = 0; ntp < 4; ntp++) {
                const int brow = wn * 64 + ntp * 16 + ((kmat >> 1) & 1) * 8 + krow;
                const int bcol = ks * 16 + (kmat & 1) * 8;
                uint32_t d0, d1, d2, d3;
                ldsm_x4(d0, d1, d2, d3, bbase + (uint32_t)(brow * GST + bcol) * 2);
                bf[2 * ntp][0] = d0;  bf[2 * ntp][1] = d1;
                bf[2 * ntp + 1][0] = d2;  bf[2 * ntp + 1][1] = d3;
            }
            #pragma unroll
            for (int nt = 0; nt < 8; nt++) {
                mma_f16(acc[0][nt], af[0], bf[nt]);
                mma_f16(acc[1][nt], af[1], bf[nt]);
            }
        }
        __syncthreads();
    }

    #pragma unroll
    for (int im = 0; im < 2; im++) {
        #pragma unroll
        for (int nt = 0; nt < 8; nt++) {
            const int m = bm + wm * 32 + im * 16 + r;
            const int n = bn + wn * 64 + nt * 8 + 2 * c;
            float2 bz = *(const float2*)&bias[n];
            float v00 = acc[im][nt][0] + bz.x, v01 = acc[im][nt][1] + bz.y;
            float v10 = acc[im][nt][2] + bz.x, v11 = acc[im][nt][3] + bz.y;
            if (mode == 0) {
                const int bb = m >> 10, ss = m & 1023;
                const int hh = n >> 6, dd = n & 63;
                __half* dst = ((mat == 0) ? g_Qh : (mat == 1) ? g_Kh : g_Vh)
                            + ((size_t)((bb * NH + hh) * SEQ + ss)) * DK + dd;
                *(uint32_t*)dst = pack_h2(v00, v01);
                *(uint32_t*)(dst + 8 * DK) = pack_h2(v10, v11);
            } else {
                float* dst = Cout + (size_t)m * 1024 + n;
                float2 a0 = { v00, v01 }, a1 = { v10, v11 };
                *(float2*)dst = a0;
                *(float2*)(dst + 8 * 1024) = a1;
            }
        }
    }
}

// ---------------------------------------------------------------------------
// Geom body (fp16 bias*log2e, mask folded) as device function.
// ---------------------------------------------------------------------------
__device__ __forceinline__ void geom_body(
    size_t gi, const float* __restrict__ geom, const float* __restrict__ Wg,
    const float* __restrict__ bg, const int* __restrict__ mask)
{
    __shared__ float wgs[7][16];
    __shared__ float bgs[16];
    int tid = threadIdx.x;
    if (tid < 112) wgs[tid / 16][tid % 16] = Wg[tid] * LOG2E;
    if (tid < 16)  bgs[tid] = bg[tid] * LOG2E;
    __syncthreads();

    size_t idx = gi * 256 + tid;
    const int k2 = (int)(idx & 511);
    const int q  = (int)((idx >> 9) & 1023);
    const int b  = (int)(idx >> 19);
    const int k  = 2 * k2;

    const float2* gp = (const float2*)(geom + ((size_t)(b * 1024 + q) * 1024 + k) * 7);
    float2 t[7];
    #pragma unroll
    for (int i = 0; i < 7; i++) t[i] = gp[i];
    float ga[7], gb[7];
    ga[0]=t[0].x; ga[1]=t[0].y; ga[2]=t[1].x; ga[3]=t[1].y; ga[4]=t[2].x; ga[5]=t[2].y; ga[6]=t[3].x;
    gb[0]=t[3].y; gb[1]=t[4].x; gb[2]=t[4].y; gb[3]=t[5].x; gb[4]=t[5].y; gb[5]=t[6].x; gb[6]=t[6].y;

    const bool live0 = mask[b * SEQ + k] != 0;
    const bool live1 = mask[b * SEQ + k + 1] != 0;
    __half2* outp = (__half2*)(g_biash + ((size_t)(b * NH) * SEQ + q) * SEQ + k);

    #pragma unroll
    for (int h = 0; h < NH; h++) {
        float va = bgs[h], vb = bgs[h];
        #pragma unroll
        for (int i = 0; i < 7; i++) {
            va += ga[i] * wgs[i][h];
            vb += gb[i] * wgs[i][h];
        }
        __half2 o = __floats2half2_rn(live0 ? va : -43000.f, live1 ? vb : -43000.f);
        outp[(size_t)h * (SEQ * SEQ / 2)] = o;
    }
}

// ---------------------------------------------------------------------------
// Fused launch: blocks [0,768) = QKV GEMM, [768, 8960) = geom bias.
// DRAM-bound geom co-schedules with compute-bound GEMM.
// ---------------------------------------------------------------------------
#define QKV_BLOCKS 768

__global__ __launch_bounds__(256)
void qkv_geom(const float* __restrict__ bq, const float* __restrict__ bk,
              const float* __restrict__ bv,
              const float* __restrict__ geom, const float* __restrict__ Wg,
              const float* __restrict__ bg, const int* __restrict__ mask)
{
    extern __shared__ __half smh[];
    if (blockIdx.x < QKV_BLOCKS) {
        const int bxg = blockIdx.x % 24;
        const int byg = blockIdx.x / 24;
        gemm_body(smh, bxg, byg, bq, bk, bv, nullptr, 0);
    } else {
        geom_body((size_t)(blockIdx.x - QKV_BLOCKS), geom, Wg, bg, mask);
    }
}

// standalone GEMM for the output projection
__global__ __launch_bounds__(256)
void gemm_h(const float* __restrict__ bias0, float* __restrict__ Cout)
{
    extern __shared__ __half smh[];
    gemm_body(smh, blockIdx.x, blockIdx.y, bias0, nullptr, nullptr, Cout, 1);
}

// ---------------------------------------------------------------------------
// fp16 flash attention (R14, unchanged): 256 thr / 8 warps, q-tile 128,
// no-max exp2 softmax, fp32 S accumulators, ones-MMA row sum,
// K/V double-buffered cp.async (wait1), bias direct from gmem.
// ---------------------------------------------------------------------------
#define AVS 72
#define KTH (64 * AVS)
#define AOFF_K(buf) ((buf) * KTH)
#define AOFF_V(buf) (2 * KTH + (buf) * KTH)
#define ASMEM_BYTES (4 * KTH * 2)                  // 36864 B
#define ONES_H2 0x3C003C00u

__global__ __launch_bounds__(256, 2)
void attn_h()
{
    extern __shared__ __half smh[];
    const uint32_t sb = smem_u32(smh);

    const int qb = blockIdx.x * 128;
    const int h  = blockIdx.y;
    const int b  = blockIdx.z;
    const __half* Qp = g_Qh + (size_t)((b * NH + h) * SEQ) * DK;
    const __half* Kp = g_Kh + (size_t)((b * NH + h) * SEQ) * DK;
    const __half* Vp = g_Vh + (size_t)((b * NH + h) * SEQ) * DK;
    const __half* Bp = g_biash + (size_t)(b * NH + h) * SEQ * SEQ;

    const int tid = threadIdx.x;
    const int lane = tid & 31, wid = tid >> 5;
    const int r = lane >> 2, c = lane & 3;
    const int q0 = wid * 16;

    const int rkv  = tid >> 2;
    const int okv  = (tid & 3) * 16;

    uint32_t qf[4][4];
    {
        const __half* qr0 = Qp + (size_t)(qb + q0 + r) * DK;
        const __half* qr1 = Qp + (size_t)(qb + q0 + r + 8) * DK;
        #pragma unroll
        for (int ks = 0; ks < 4; ks++) {
            qf[ks][0] = *(const uint32_t*)&qr0[ks * 16 + 2 * c];
            qf[ks][1] = *(const uint32_t*)&qr1[ks * 16 + 2 * c];
            qf[ks][2] = *(const uint32_t*)&qr0[ks * 16 + 2 * c + 8];
            qf[ks][3] = *(const uint32_t*)&qr1[ks * 16 + 2 * c + 8];
        }
    }

    {
        const __half* Kg = Kp + (size_t)rkv * DK + okv;
        const __half* Vg = Vp + (size_t)rkv * DK + okv;
        uint32_t kd = sb + (uint32_t)(AOFF_K(0) + rkv * AVS + okv) * 2;
        uint32_t vd = sb + (uint32_t)(AOFF_V(0) + rkv * AVS + okv) * 2;
        cp_async16(kd, Kg);       cp_async16(kd + 16, Kg + 8);
        cp_async16(vd, Vg);       cp_async16(vd + 16, Vg + 8);
        cp_commit();
    }

    float oAcc[8][4];
    #pragma unroll
    for (int dt = 0; dt < 8; dt++)
        #pragma unroll
        for (int j = 0; j < 4; j++) oAcc[dt][j] = 0.f;
    float lAcc[4] = { 0.f, 0.f, 0.f, 0.f };

    const float SC = 0.125f * LOG2E;
    const int kmat = lane >> 3;
    const int krow_in = lane & 7;

    for (int kt = 0; kt < 16; kt++) {
        if (kt < 15) {
            const int buf = (kt + 1) & 1;
            const int kb2 = (kt + 1) * 64;
            const __half* Kg = Kp + (size_t)(kb2 + rkv) * DK + okv;
            const __half* Vg = Vp + (size_t)(kb2 + rkv) * DK + okv;
            uint32_t kd = sb + (uint32_t)(AOFF_K(buf) + rkv * AVS + okv) * 2;
            uint32_t vd = sb + (uint32_t)(AOFF_V(buf) + rkv * AVS + okv) * 2;
            cp_async16(kd, Kg);       cp_async16(kd + 16, Kg + 8);
            cp_async16(vd, Vg);       cp_async16(vd + 16, Vg + 8);
        }
        cp_commit();
        cp_wait1();
        __syncthreads();

        const int buf = kt & 1;
        const uint32_t kbase = sb + (uint32_t)AOFF_K(buf) * 2;
        const uint32_t vbase = sb + (uint32_t)AOFF_V(buf) * 2;
        const __half* Bg0 = Bp + (size_t)(qb + q0 + r) * SEQ + kt * 64;
        const __half* Bg1 = Bg0 + (size_t)8 * SEQ;

        float sAcc[8][4];
        #pragma unroll
        for (int nt = 0; nt < 8; nt++)
            #pragma unroll
            for (int j = 0; j < 4; j++) sAcc[nt][j] = 0.f;

        #pragma unroll
        for (int ks = 0; ks < 4; ks++) {
            #pragma unroll
            for (int ntp = 0; ntp < 4; ntp++) {
                const int seqrow = ntp * 16 + ((kmat >> 1) & 1) * 8 + krow_in;
                const int col = ks * 16 + (kmat & 1) * 8;
                uint32_t addr = kbase + (uint32_t)(seqrow * AVS + col) * 2;
                uint32_t d0, d1, d2, d3;
                ldsm_x4(d0, d1, d2, d3, addr);
                uint32_t b01[2] = { d0, d1 };
                uint32_t b23[2] = { d2, d3 };
                mma_f16(sAcc[2 * ntp],     qf[ks], b01);
                mma_f16(sAcc[2 * ntp + 1], qf[ks], b23);
            }
        }

        __half2 hA[8], hB[8];
        #pragma unroll
        for (int nt = 0; nt < 8; nt++) {
            uint32_t uA = *(const uint32_t*)(Bg0 + nt * 8 + 2 * c);
            uint32_t uB = *(const uint32_t*)(Bg1 + nt * 8 + 2 * c);
            float2 bzA = __half22float2(bits2h2(uA));
            float2 bzB = __half22float2(bits2h2(uB));
            hA[nt] = __floats2half2_rn(fmaf(sAcc[nt][0], SC, bzA.x),
                                       fmaf(sAcc[nt][1], SC, bzA.y));
            hB[nt] = __floats2half2_rn(fmaf(sAcc[nt][2], SC, bzB.x),
                                       fmaf(sAcc[nt][3], SC, bzB.y));
        }

        const uint32_t ones[2] = { ONES_H2, ONES_H2 };
        #pragma unroll
        for (int ks = 0; ks < 4; ks++) {
            uint32_t pa[4];
            pa[0] = h2bits(h2exp2(hA[2 * ks]));
            pa[1] = h2bits(h2exp2(hB[2 * ks]));
            pa[2] = h2bits(h2exp2(hA[2 * ks + 1]));
            pa[3] = h2bits(h2exp2(hB[2 * ks + 1]));
            mma_f16(lAcc, pa, ones);                  // exact fp32 row-sum of fp16 P
            #pragma unroll
            for (int dtp = 0; dtp < 4; dtp++) {
                const int vrow = ks * 16 + (kmat & 1) * 8 + krow_in;
                const int vcol = dtp * 16 + ((kmat >> 1) & 1) * 8;
                uint32_t addr = vbase + (uint32_t)(vrow * AVS + vcol) * 2;
                uint32_t d0, d1, d2, d3;
                ldsm_x4_t(d0, d1, d2, d3, addr);
                uint32_t b01[2] = { d0, d1 };
                uint32_t b23[2] = { d2, d3 };
                mma_f16(oAcc[2 * dtp],     pa, b01);
                mma_f16(oAcc[2 * dtp + 1], pa, b23);
            }
        }
        __syncthreads();
    }

    const float iA = 1.f / lAcc[0];
    const float iB = 1.f / lAcc[2];
    __half* Op0 = g_ctxh + (size_t)(b * SEQ + qb + q0 + r) * DMODEL + h * 64 + 2 * c;
    __half* Op1 = Op0 + (size_t)8 * DMODEL;
    #pragma unroll
    for (int dt = 0; dt < 8; dt++) {
        *(uint32_t*)(Op0 + dt * 8) = pack_h2(oAcc[dt][0] * iA, oAcc[dt][1] * iA);
        *(uint32_t*)(Op1 + dt * 8) = pack_h2(oAcc[dt][2] * iB, oAcc[dt][3] * iB);
    }
}

// ---------------------------------------------------------------------------
extern "C" void kernel_launch(void* const* d_in, const int* in_sizes, int n_in,
                              void* d_out, int out_size)
{
    const float* x    = (const float*)d_in[0];
    const float* geom = (const float*)d_in[1];
    const int*   mask = (const int*)d_in[2];
    const float* Wq = (const float*)d_in[3];
    const float* bq = (const float*)d_in[4];
    const float* Wk = (const float*)d_in[5];
    const float* bk = (const float*)d_in[6];
    const float* Wv = (const float*)d_in[7];
    const float* bv = (const float*)d_in[8];
    const float* Wo = (const float*)d_in[9];
    const float* bo = (const float*)d_in[10];
    const float* Wg = (const float*)d_in[11];
    const float* bg = (const float*)d_in[12];
    float* out = (float*)d_out;

    cudaFuncSetAttribute(qkv_geom, cudaFuncAttributeMaxDynamicSharedMemorySize, GSMEM_BYTES);
    cudaFuncSetAttribute(gemm_h, cudaFuncAttributeMaxDynamicSharedMemorySize, GSMEM_BYTES);
    cudaFuncSetAttribute(attn_h, cudaFuncAttributeMaxDynamicSharedMemorySize, ASMEM_BYTES);

    // launch 1: prep (x convert + 4 weight transposes)
    prep<<<dim3(32, 32, 5), dim3(32, 8)>>>(x, Wq, Wk, Wv, Wo);

    // launch 2: fused QKV GEMM (768 blocks) + geom bias (8192 blocks)
    qkv_geom<<<QKV_BLOCKS + (BATCH * SEQ * SEQ / 2) / 256, 256, GSMEM_BYTES>>>(
        bq, bk, bv, geom, Wg, bg, mask);

    // launch 3: attention
    attn_h<<<dim3(SEQ / 128, NH, BATCH), 256, ASMEM_BYTES>>>();

    // launch 4: output projection (profiled slot)
    gemm_h<<<dim3(8, 32), 256, GSMEM_BYTES>>>(bo, out);
}

// round 16
// speedup vs baseline: 1.3729x; 1.0140x over previous
#include <cuda_runtime.h>
#include <cuda_fp16.h>
#include <math.h>
#include <cstdint>

#define BATCH  4
#define SEQ    1024
#define DMODEL 1024
#define NH     16
#define DK     64
#define LOG2E  1.4426950408889634f

// ---------------- scratch (device globals: allocation-free) ----------------
__device__ __half g_xh[BATCH * SEQ * DMODEL];
__device__ __half g_WTh[4 * 1024 * 1024];     // W^T per matrix: [n][k] fp16
__device__ __half g_Qh[BATCH * NH * SEQ * DK];
__device__ __half g_Kh[BATCH * NH * SEQ * DK];
__device__ __half g_Vh[BATCH * NH * SEQ * DK];
__device__ __half g_ctxh[BATCH * SEQ * DMODEL];
__device__ __half g_biash[(size_t)BATCH * NH * SEQ * SEQ];  // bias*log2e, mask folded

// ---------------- helpers ----------------
__device__ __forceinline__ void mma_f16(float c[4], const uint32_t a[4], const uint32_t b[2]) {
    asm volatile("mma.sync.aligned.m16n8k16.row.col.f32.f16.f16.f32 "
                 "{%0,%1,%2,%3}, {%4,%5,%6,%7}, {%8,%9}, {%0,%1,%2,%3};"
                 : "+f"(c[0]), "+f"(c[1]), "+f"(c[2]), "+f"(c[3])
                 : "r"(a[0]), "r"(a[1]), "r"(a[2]), "r"(a[3]), "r"(b[0]), "r"(b[1]));
}
__device__ __forceinline__ uint32_t smem_u32(const void* p) {
    uint32_t a;
    asm("{ .reg .u64 t; cvta.to.shared.u64 t, %1; cvt.u32.u64 %0, t; }" : "=r"(a) : "l"(p));
    return a;
}
__device__ __forceinline__ void cp_async16(uint32_t s, const void* g) {
    asm volatile("cp.async.cg.shared.global [%0], [%1], 16;" :: "r"(s), "l"(g) : "memory");
}
__device__ __forceinline__ void cp_commit() {
    asm volatile("cp.async.commit_group;" ::: "memory");
}
__device__ __forceinline__ void cp_wait1() {
    asm volatile("cp.async.wait_group 1;" ::: "memory");
}
__device__ __forceinline__ void ldsm_x4(uint32_t& d0, uint32_t& d1, uint32_t& d2, uint32_t& d3,
                                        uint32_t addr) {
    asm volatile("ldmatrix.sync.aligned.m8n8.x4.shared.b16 {%0,%1,%2,%3}, [%4];"
                 : "=r"(d0), "=r"(d1), "=r"(d2), "=r"(d3) : "r"(addr));
}
__device__ __forceinline__ void ldsm_x4_t(uint32_t& d0, uint32_t& d1, uint32_t& d2, uint32_t& d3,
                                          uint32_t addr) {
    asm volatile("ldmatrix.sync.aligned.m8n8.x4.trans.shared.b16 {%0,%1,%2,%3}, [%4];"
                 : "=r"(d0), "=r"(d1), "=r"(d2), "=r"(d3) : "r"(addr));
}
__device__ __forceinline__ uint32_t pack_h2(float lo, float hi) {
    __half2 h = __floats2half2_rn(lo, hi);
    return *(uint32_t*)&h;
}
__device__ __forceinline__ uint32_t h2bits(__half2 h) { return *(uint32_t*)&h; }
__device__ __forceinline__ __half2 bits2h2(uint32_t u) { return *(__half2*)&u; }

// ---------------------------------------------------------------------------
// prep: z<4 -> weight transpose+convert; z==4 -> x fp32->fp16
// ---------------------------------------------------------------------------
__global__ void prep(const float* __restrict__ x,
                     const float* __restrict__ W0, const float* __restrict__ W1,
                     const float* __restrict__ W2, const float* __restrict__ W3)
{
    if (blockIdx.z < 4) {
        __shared__ float t[32][33];
        const float* W = (blockIdx.z == 0) ? W0 : (blockIdx.z == 1) ? W1
                       : (blockIdx.z == 2) ? W2 : W3;
        __half* Wt = g_WTh + (size_t)blockIdx.z * 1024 * 1024;
        int bx = blockIdx.x * 32, by = blockIdx.y * 32;
        int tx = threadIdx.x, ty = threadIdx.y;
        #pragma unroll
        for (int i = 0; i < 32; i += 8)
            t[ty + i][tx] = W[(size_t)(by + ty + i) * 1024 + bx + tx];
        __syncthreads();
        #pragma unroll
        for (int i = 0; i < 32; i += 8)
            Wt[(size_t)(bx + ty + i) * 1024 + by + tx] = __float2half(t[tx][ty + i]);
    } else {
        const int tid = threadIdx.y * 32 + threadIdx.x;
        size_t base = (((size_t)blockIdx.y * 32 + blockIdx.x) * 256 + tid) * 16;
        #pragma unroll
        for (int j = 0; j < 4; j++) {
            float4 v = *(const float4*)(x + base + j * 4);
            *(uint32_t*)&g_xh[base + j * 4]     = pack_h2(v.x, v.y);
            *(uint32_t*)&g_xh[base + j * 4 + 2] = pack_h2(v.z, v.w);
        }
    }
}

// ---------------------------------------------------------------------------
// GEMM body (m16n8k16, k-slab 32, GST 40) as an inlineable device function.
// mode 0: QKV (mat 0..2), mode 1: outproj -> fp32 Cout.
// ---------------------------------------------------------------------------
#define GST 40
#define GBUFH (2 * 128 * GST)
#define GSMEM_BYTES (2 * GBUFH * 2)              // 40960 B

__device__ __forceinline__ void gemm_body(
    __half* smh, int bxg, int byg,
    const float* bias0, const float* bias1, const float* bias2,
    float* Cout, int mode)
{
    const uint32_t sb = smem_u32(smh);
    const int tid = threadIdx.x, lane = tid & 31;
    const int wid = tid >> 5;
    const int wm = wid & 3, wn = wid >> 2;
    const int r = lane >> 2, c = lane & 3;
    const int kmat = lane >> 3, krow = lane & 7;

    int mat, bn;
    const float* bias;
    if (mode == 0) {
        mat = bxg >> 3;
        bn = (bxg & 7) * 128;
        bias = (mat == 0) ? bias0 : (mat == 1) ? bias1 : bias2;
    } else {
        mat = 3;
        bn = bxg * 128;
        bias = bias0;
    }
    const int bm = byg * 128;
    const __half* Ah = (mode == 0) ? g_xh : g_ctxh;
    const __half* Bh = g_WTh + (size_t)mat * 1024 * 1024;

    const int row = tid >> 1;
    const int off = (tid & 1) * 16;

    const __half* Ag0 = Ah + (size_t)(bm + row) * 1024 + off;
    const __half* Bg0 = Bh + (size_t)(bn + row) * 1024 + off;

    {
        uint32_t ad = sb + (uint32_t)(row * GST + off) * 2;
        uint32_t bd = sb + (uint32_t)(128 * GST + row * GST + off) * 2;
        cp_async16(ad, Ag0);       cp_async16(ad + 16, Ag0 + 8);
        cp_async16(bd, Bg0);       cp_async16(bd + 16, Bg0 + 8);
        cp_commit();
    }

    float acc[2][8][4];
    #pragma unroll
    for (int im = 0; im < 2; im++)
        #pragma unroll
        for (int nt = 0; nt < 8; nt++)
            #pragma unroll
            for (int j = 0; j < 4; j++) acc[im][nt][j] = 0.f;

    for (int s = 0; s < 32; s++) {
        if (s < 31) {
            const int buf = (s + 1) & 1;
            const int k0 = (s + 1) * 32;
            uint32_t ad = sb + (uint32_t)(buf * GBUFH + row * GST + off) * 2;
            uint32_t bd = sb + (uint32_t)(buf * GBUFH + 128 * GST + row * GST + off) * 2;
            cp_async16(ad, Ag0 + k0);       cp_async16(ad + 16, Ag0 + k0 + 8);
            cp_async16(bd, Bg0 + k0);       cp_async16(bd + 16, Bg0 + k0 + 8);
        }
        cp_commit();
        cp_wait1();
        __syncthreads();

        const uint32_t abase = sb + (uint32_t)((s & 1) * GBUFH) * 2;
        const uint32_t bbase = abase + (uint32_t)(128 * GST) * 2;
        #pragma unroll
        for (int ks = 0; ks < 2; ks++) {
            uint32_t af[2][4];
            #pragma unroll
            for (int im = 0; im < 2; im++) {
                const int arow = wm * 32 + im * 16 + (kmat & 1) * 8 + krow;
                const int acol = ks * 16 + (kmat >> 1) * 8;
                ldsm_x4(af[im][0], af[im][1], af[im][2], af[im][3],
                        abase + (uint32_t)(arow * GST + acol) * 2);
            }
            uint32_t bf[8][2];
            #pragma unroll
            for (int ntp = 0; ntp < 4; ntp++) {
                const int brow = wn * 64 + ntp * 16 + ((kmat >> 1) & 1) * 8 + krow;
                const int bcol = ks * 16 + (kmat & 1) * 8;
                uint32_t d0, d1, d2, d3;
                ldsm_x4(d0, d1, d2, d3, bbase + (uint32_t)(brow * GST + bcol) * 2);
                bf[2 * ntp][0] = d0;  bf[2 * ntp][1] = d1;
                bf[2 * ntp + 1][0] = d2;  bf[2 * ntp + 1][1] = d3;
            }
            #pragma unroll
            for (int nt = 0; nt < 8; nt++) {
                mma_f16(acc[0][nt], af[0], bf[nt]);
                mma_f16(acc[1][nt], af[1], bf[nt]);
            }
        }
        __syncthreads();
    }

    #pragma unroll
    for (int im = 0; im < 2; im++) {
        #pragma unroll
        for (int nt = 0; nt < 8; nt++) {
            const int m = bm + wm * 32 + im * 16 + r;
            const int n = bn + wn * 64 + nt * 8 + 2 * c;
            float2 bz = *(const float2*)&bias[n];
            float v00 = acc[im][nt][0] + bz.x, v01 = acc[im][nt][1] + bz.y;
            float v10 = acc[im][nt][2] + bz.x, v11 = acc[im][nt][3] + bz.y;
            if (mode == 0) {
                const int bb = m >> 10, ss = m & 1023;
                const int hh = n >> 6, dd = n & 63;
                __half* dst = ((mat == 0) ? g_Qh : (mat == 1) ? g_Kh : g_Vh)
                            + ((size_t)((bb * NH + hh) * SEQ + ss)) * DK + dd;
                *(uint32_t*)dst = pack_h2(v00, v01);
                *(uint32_t*)(dst + 8 * DK) = pack_h2(v10, v11);
            } else {
                float* dst = Cout + (size_t)m * 1024 + n;
                float2 a0 = { v00, v01 }, a1 = { v10, v11 };
                *(float2*)dst = a0;
                *(float2*)(dst + 8 * 1024) = a1;
            }
        }
    }
}

// ---------------------------------------------------------------------------
// Geom body (fp16 bias*log2e, mask folded) as device function.
// ---------------------------------------------------------------------------
__device__ __forceinline__ void geom_body(
    size_t gi, const float* __restrict__ geom, const float* __restrict__ Wg,
    const float* __restrict__ bg, const int* __restrict__ mask)
{
    __shared__ float wgs[7][16];
    __shared__ float bgs[16];
    int tid = threadIdx.x;
    if (tid < 112) wgs[tid / 16][tid % 16] = Wg[tid] * LOG2E;
    if (tid < 16)  bgs[tid] = bg[tid] * LOG2E;
    __syncthreads();

    size_t idx = gi * 256 + tid;
    const int k2 = (int)(idx & 511);
    const int q  = (int)((idx >> 9) & 1023);
    const int b  = (int)(idx >> 19);
    const int k  = 2 * k2;

    const float2* gp = (const float2*)(geom + ((size_t)(b * 1024 + q) * 1024 + k) * 7);
    float2 t[7];
    #pragma unroll
    for (int i = 0; i < 7; i++) t[i] = gp[i];
    float ga[7], gb[7];
    ga[0]=t[0].x; ga[1]=t[0].y; ga[2]=t[1].x; ga[3]=t[1].y; ga[4]=t[2].x; ga[5]=t[2].y; ga[6]=t[3].x;
    gb[0]=t[3].y; gb[1]=t[4].x; gb[2]=t[4].y; gb[3]=t[5].x; gb[4]=t[5].y; gb[5]=t[6].x; gb[6]=t[6].y;

    const bool live0 = mask[b * SEQ + k] != 0;
    const bool live1 = mask[b * SEQ + k + 1] != 0;
    __half2* outp = (__half2*)(g_biash + ((size_t)(b * NH) * SEQ + q) * SEQ + k);

    #pragma unroll
    for (int h = 0; h < NH; h++) {
        float va = bgs[h], vb = bgs[h];
        #pragma unroll
        for (int i = 0; i < 7; i++) {
            va += ga[i] * wgs[i][h];
            vb += gb[i] * wgs[i][h];
        }
        __half2 o = __floats2half2_rn(live0 ? va : -43000.f, live1 ? vb : -43000.f);
        outp[(size_t)h * (SEQ * SEQ / 2)] = o;
    }
}

// ---------------------------------------------------------------------------
// Fused launch: blocks [0,768) = QKV GEMM, [768, 8960) = geom bias.
// launch_bounds(256,2): cap regs at 128 so 2 CTAs fit per SM (R15 had 130).
// ---------------------------------------------------------------------------
#define QKV_BLOCKS 768

__global__ __launch_bounds__(256, 2)
void qkv_geom(const float* __restrict__ bq, const float* __restrict__ bk,
              const float* __restrict__ bv,
              const float* __restrict__ geom, const float* __restrict__ Wg,
              const float* __restrict__ bg, const int* __restrict__ mask)
{
    extern __shared__ __half smh[];
    if (blockIdx.x < QKV_BLOCKS) {
        const int bxg = blockIdx.x % 24;
        const int byg = blockIdx.x / 24;
        gemm_body(smh, bxg, byg, bq, bk, bv, nullptr, 0);
    } else {
        geom_body((size_t)(blockIdx.x - QKV_BLOCKS), geom, Wg, bg, mask);
    }
}

// standalone GEMM for the output projection
__global__ __launch_bounds__(256, 2)
void gemm_h(const float* __restrict__ bias0, float* __restrict__ Cout)
{
    extern __shared__ __half smh[];
    gemm_body(smh, blockIdx.x, blockIdx.y, bias0, nullptr, nullptr, Cout, 1);
}

// ---------------------------------------------------------------------------
// fp16 flash attention (R14, unchanged): 256 thr / 8 warps, q-tile 128,
// no-max exp2 softmax, fp32 S accumulators, ones-MMA row sum,
// K/V double-buffered cp.async (wait1), bias direct from gmem.
// ---------------------------------------------------------------------------
#define AVS 72
#define KTH (64 * AVS)
#define AOFF_K(buf) ((buf) * KTH)
#define AOFF_V(buf) (2 * KTH + (buf) * KTH)
#define ASMEM_BYTES (4 * KTH * 2)                  // 36864 B
#define ONES_H2 0x3C003C00u

__global__ __launch_bounds__(256, 2)
void attn_h()
{
    extern __shared__ __half smh[];
    const uint32_t sb = smem_u32(smh);

    const int qb = blockIdx.x * 128;
    const int h  = blockIdx.y;
    const int b  = blockIdx.z;
    const __half* Qp = g_Qh + (size_t)((b * NH + h) * SEQ) * DK;
    const __half* Kp = g_Kh + (size_t)((b * NH + h) * SEQ) * DK;
    const __half* Vp = g_Vh + (size_t)((b * NH + h) * SEQ) * DK;
    const __half* Bp = g_biash + (size_t)(b * NH + h) * SEQ * SEQ;

    const int tid = threadIdx.x;
    const int lane = tid & 31, wid = tid >> 5;
    const int r = lane >> 2, c = lane & 3;
    const int q0 = wid * 16;

    const int rkv  = tid >> 2;
    const int okv  = (tid & 3) * 16;

    uint32_t qf[4][4];
    {
        const __half* qr0 = Qp + (size_t)(qb + q0 + r) * DK;
        const __half* qr1 = Qp + (size_t)(qb + q0 + r + 8) * DK;
        #pragma unroll
        for (int ks = 0; ks < 4; ks++) {
            qf[ks][0] = *(const uint32_t*)&qr0[ks * 16 + 2 * c];
            qf[ks][1] = *(const uint32_t*)&qr1[ks * 16 + 2 * c];
            qf[ks][2] = *(const uint32_t*)&qr0[ks * 16 + 2 * c + 8];
            qf[ks][3] = *(const uint32_t*)&qr1[ks * 16 + 2 * c + 8];
        }
    }

    {
        const __half* Kg = Kp + (size_t)rkv * DK + okv;
        const __half* Vg = Vp + (size_t)rkv * DK + okv;
        uint32_t kd = sb + (uint32_t)(AOFF_K(0) + rkv * AVS + okv) * 2;
        uint32_t vd = sb + (uint32_t)(AOFF_V(0) + rkv * AVS + okv) * 2;
        cp_async16(kd, Kg);       cp_async16(kd + 16, Kg + 8);
        cp_async16(vd, Vg);       cp_async16(vd + 16, Vg + 8);
        cp_commit();
    }

    float oAcc[8][4];
    #pragma unroll
    for (int dt = 0; dt < 8; dt++)
        #pragma unroll
        for (int j = 0; j < 4; j++) oAcc[dt][j] = 0.f;
    float lAcc[4] = { 0.f, 0.f, 0.f, 0.f };

    const float SC = 0.125f * LOG2E;
    const int kmat = lane >> 3;
    const int krow_in = lane & 7;

    for (int kt = 0; kt < 16; kt++) {
        if (kt < 15) {
            const int buf = (kt + 1) & 1;
            const int kb2 = (kt + 1) * 64;
            const __half* Kg = Kp + (size_t)(kb2 + rkv) * DK + okv;
            const __half* Vg = Vp + (size_t)(kb2 + rkv) * DK + okv;
            uint32_t kd = sb + (uint32_t)(AOFF_K(buf) + rkv * AVS + okv) * 2;
            uint32_t vd = sb + (uint32_t)(AOFF_V(buf) + rkv * AVS + okv) * 2;
            cp_async16(kd, Kg);       cp_async16(kd + 16, Kg + 8);
            cp_async16(vd, Vg);       cp_async16(vd + 16, Vg + 8);
        }
        cp_commit();
        cp_wait1();
        __syncthreads();

        const int buf = kt & 1;
        const uint32_t kbase = sb + (uint32_t)AOFF_K(buf) * 2;
        const uint32_t vbase = sb + (uint32_t)AOFF_V(buf) * 2;
        const __half* Bg0 = Bp + (size_t)(qb + q0 + r) * SEQ + kt * 64;
        const __half* Bg1 = Bg0 + (size_t)8 * SEQ;

        float sAcc[8][4];
        #pragma unroll
        for (int nt = 0; nt < 8; nt++)
            #pragma unroll
            for (int j = 0; j < 4; j++) sAcc[nt][j] = 0.f;

        #pragma unroll
        for (int ks = 0; ks < 4; ks++) {
            #pragma unroll
            for (int ntp = 0; ntp < 4; ntp++) {
                const int seqrow = ntp * 16 + ((kmat >> 1) & 1) * 8 + krow_in;
                const int col = ks * 16 + (kmat & 1) * 8;
                uint32_t addr = kbase + (uint32_t)(seqrow * AVS + col) * 2;
                uint32_t d0, d1, d2, d3;
                ldsm_x4(d0, d1, d2, d3, addr);
                uint32_t b01[2] = { d0, d1 };
                uint32_t b23[2] = { d2, d3 };
                mma_f16(sAcc[2 * ntp],     qf[ks], b01);
                mma_f16(sAcc[2 * ntp + 1], qf[ks], b23);
            }
        }

        __half2 hA[8], hB[8];
        #pragma unroll
        for (int nt = 0; nt < 8; nt++) {
            uint32_t uA = *(const uint32_t*)(Bg0 + nt * 8 + 2 * c);
            uint32_t uB = *(const uint32_t*)(Bg1 + nt * 8 + 2 * c);
            float2 bzA = __half22float2(bits2h2(uA));
            float2 bzB = __half22float2(bits2h2(uB));
            hA[nt] = __floats2half2_rn(fmaf(sAcc[nt][0], SC, bzA.x),
                                       fmaf(sAcc[nt][1], SC, bzA.y));
            hB[nt] = __floats2half2_rn(fmaf(sAcc[nt][2], SC, bzB.x),
                                       fmaf(sAcc[nt][3], SC, bzB.y));
        }

        const uint32_t ones[2] = { ONES_H2, ONES_H2 };
        #pragma unroll
        for (int ks = 0; ks < 4; ks++) {
            uint32_t pa[4];
            pa[0] = h2bits(h2exp2(hA[2 * ks]));
            pa[1] = h2bits(h2exp2(hB[2 * ks]));
            pa[2] = h2bits(h2exp2(hA[2 * ks + 1]));
            pa[3] = h2bits(h2exp2(hB[2 * ks + 1]));
            mma_f16(lAcc, pa, ones);                  // exact fp32 row-sum of fp16 P
            #pragma unroll
            for (int dtp = 0; dtp < 4; dtp++) {
                const int vrow = ks * 16 + (kmat & 1) * 8 + krow_in;
                const int vcol = dtp * 16 + ((kmat >> 1) & 1) * 8;
                uint32_t addr = vbase + (uint32_t)(vrow * AVS + vcol) * 2;
                uint32_t d0, d1, d2, d3;
                ldsm_x4_t(d0, d1, d2, d3, addr);
                uint32_t b01[2] = { d0, d1 };
                uint32_t b23[2] = { d2, d3 };
                mma_f16(oAcc[2 * dtp],     pa, b01);
                mma_f16(oAcc[2 * dtp + 1], pa, b23);
            }
        }
        __syncthreads();
    }

    const float iA = 1.f / lAcc[0];
    const float iB = 1.f / lAcc[2];
    __half* Op0 = g_ctxh + (size_t)(b * SEQ + qb + q0 + r) * DMODEL + h * 64 + 2 * c;
    __half* Op1 = Op0 + (size_t)8 * DMODEL;
    #pragma unroll
    for (int dt = 0; dt < 8; dt++) {
        *(uint32_t*)(Op0 + dt * 8) = pack_h2(oAcc[dt][0] * iA, oAcc[dt][1] * iA);
        *(uint32_t*)(Op1 + dt * 8) = pack_h2(oAcc[dt][2] * iB, oAcc[dt][3] * iB);
    }
}

// ---------------------------------------------------------------------------
extern "C" void kernel_launch(void* const* d_in, const int* in_sizes, int n_in,
                              void* d_out, int out_size)
{
    const float* x    = (const float*)d_in[0];
    const float* geom = (const float*)d_in[1];
    const int*   mask = (const int*)d_in[2];
    const float* Wq = (const float*)d_in[3];
    const float* bq = (const float*)d_in[4];
    const float* Wk = (const float*)d_in[5];
    const float* bk = (const float*)d_in[6];
    const float* Wv = (const float*)d_in[7];
    const float* bv = (const float*)d_in[8];
    const float* Wo = (const float*)d_in[9];
    const float* bo = (const float*)d_in[10];
    const float* Wg = (const float*)d_in[11];
    const float* bg = (const float*)d_in[12];
    float* out = (float*)d_out;

    cudaFuncSetAttribute(qkv_geom, cudaFuncAttributeMaxDynamicSharedMemorySize, GSMEM_BYTES);
    cudaFuncSetAttribute(gemm_h, cudaFuncAttributeMaxDynamicSharedMemorySize, GSMEM_BYTES);
    cudaFuncSetAttribute(attn_h, cudaFuncAttributeMaxDynamicSharedMemorySize, ASMEM_BYTES);

    // launch 1: prep (x convert + 4 weight transposes)
    prep<<<dim3(32, 32, 5), dim3(32, 8)>>>(x, Wq, Wk, Wv, Wo);

    // launch 2: fused QKV GEMM (768 blocks) + geom bias (8192 blocks)
    qkv_geom<<<QKV_BLOCKS + (BATCH * SEQ * SEQ / 2) / 256, 256, GSMEM_BYTES>>>(
        bq, bk, bv, geom, Wg, bg, mask);

    // launch 3: attention
    attn_h<<<dim3(SEQ / 128, NH, BATCH), 256, ASMEM_BYTES>>>();

    // launch 4: output projection (profiled slot)
    gemm_h<<<dim3(8, 32), 256, GSMEM_BYTES>>>(bo, out);
}